// round 2
// baseline (speedup 1.0000x reference)
#include <cuda_runtime.h>
#include <cuda_bf16.h>

#define BATCH   4
#define NBOX    8192
#define TILE    256
#define THREADS 256

// Scratch for the adjusted-score vector (no device allocs allowed).
__device__ float g_adjusted[BATCH * NBOX];

// ---------------------------------------------------------------------------
// Kernel 1: adjusted[b][i] = sum_j exp(-iou(i,j)/0.5) * scores[b][j]
// Fused: never materializes the N x N matrix.
// ---------------------------------------------------------------------------
__global__ __launch_bounds__(THREADS)
void adjusted_kernel(const float* __restrict__ boxes,
                     const float* __restrict__ scores)
{
    const int b = blockIdx.y;
    const int i = blockIdx.x * THREADS + threadIdx.x;

    const float4* __restrict__ box4 = reinterpret_cast<const float4*>(boxes) + (size_t)b * NBOX;
    const float*  __restrict__ sc   = scores + (size_t)b * NBOX;

    const float4 bi    = box4[i];
    const float  areai = (bi.z - bi.x) * (bi.w - bi.y);

    __shared__ float4 sbox[TILE];
    __shared__ float2 sas[TILE];   // (area_j, score_j)

    // exp(-iou/0.5) = exp2( iou * (-2/ln2) )
    const float C = -2.8853900817779268f;

    float acc  = 0.0f;   // Kahan-compensated across tiles (order-stable)
    float comp = 0.0f;

    for (int j0 = 0; j0 < NBOX; j0 += TILE) {
        __syncthreads();
        {
            float4 bj = box4[j0 + threadIdx.x];
            sbox[threadIdx.x] = bj;
            sas[threadIdx.x]  = make_float2((bj.z - bj.x) * (bj.w - bj.y),
                                            sc[j0 + threadIdx.x]);
        }
        __syncthreads();

        float part = 0.0f;
        #pragma unroll 8
        for (int j = 0; j < TILE; ++j) {
            const float4 bj = sbox[j];
            const float2 as = sas[j];
            float iw = fmaxf(fminf(bi.z, bj.z) - fmaxf(bi.x, bj.x), 0.0f);
            float ih = fmaxf(fminf(bi.w, bj.w) - fmaxf(bi.y, bj.y), 0.0f);
            float inter = iw * ih;
            float uni   = (areai + as.x) - inter;
            float t     = __fdividef(inter, uni) * C;
            float w;
            asm("ex2.approx.ftz.f32 %0, %1;" : "=f"(w) : "f"(t));
            part = fmaf(w, as.y, part);
        }

        // Kahan add of tile partial (use __f*_rn so it can't be reassociated)
        float y = __fsub_rn(part, comp);
        float s = __fadd_rn(acc, y);
        comp    = __fsub_rn(__fsub_rn(s, acc), y);
        acc     = s;
    }

    g_adjusted[b * NBOX + i] = acc;
}

// ---------------------------------------------------------------------------
// Kernel 2: per-batch softmax(adjusted) and weighted box average.
// out[b] = sum_i softmax(adjusted)[i] * boxes[b][i]
// ---------------------------------------------------------------------------
__global__ __launch_bounds__(1024)
void softmax_out_kernel(const float* __restrict__ boxes,
                        float* __restrict__ out)
{
    const int b = blockIdx.x;
    const int t = threadIdx.x;
    const float* __restrict__ adj  = g_adjusted + b * NBOX;
    const float4* __restrict__ box4 = reinterpret_cast<const float4*>(boxes) + (size_t)b * NBOX;

    __shared__ float sred[32];
    __shared__ float s5[5][32];

    // ---- block max ----
    float m = -3.4e38f;
    for (int i = t; i < NBOX; i += 1024) m = fmaxf(m, adj[i]);
    #pragma unroll
    for (int o = 16; o; o >>= 1) m = fmaxf(m, __shfl_xor_sync(0xffffffffu, m, o));
    if ((t & 31) == 0) sred[t >> 5] = m;
    __syncthreads();
    if (t < 32) {
        float v = sred[t];
        #pragma unroll
        for (int o = 16; o; o >>= 1) v = fmaxf(v, __shfl_xor_sync(0xffffffffu, v, o));
        if (t == 0) sred[0] = v;
    }
    __syncthreads();
    m = sred[0];

    // ---- weighted sums ----
    float se = 0.f, sx1 = 0.f, sy1 = 0.f, sx2 = 0.f, sy2 = 0.f;
    for (int i = t; i < NBOX; i += 1024) {
        float e = __expf(adj[i] - m);
        float4 bx = box4[i];
        se  += e;
        sx1 = fmaf(e, bx.x, sx1);
        sy1 = fmaf(e, bx.y, sy1);
        sx2 = fmaf(e, bx.z, sx2);
        sy2 = fmaf(e, bx.w, sy2);
    }
    #pragma unroll
    for (int o = 16; o; o >>= 1) {
        se  += __shfl_xor_sync(0xffffffffu, se,  o);
        sx1 += __shfl_xor_sync(0xffffffffu, sx1, o);
        sy1 += __shfl_xor_sync(0xffffffffu, sy1, o);
        sx2 += __shfl_xor_sync(0xffffffffu, sx2, o);
        sy2 += __shfl_xor_sync(0xffffffffu, sy2, o);
    }
    if ((t & 31) == 0) {
        int w = t >> 5;
        s5[0][w] = se; s5[1][w] = sx1; s5[2][w] = sy1; s5[3][w] = sx2; s5[4][w] = sy2;
    }
    __syncthreads();
    if (t < 32) {
        float a0 = s5[0][t], a1 = s5[1][t], a2 = s5[2][t], a3 = s5[3][t], a4 = s5[4][t];
        #pragma unroll
        for (int o = 16; o; o >>= 1) {
            a0 += __shfl_xor_sync(0xffffffffu, a0, o);
            a1 += __shfl_xor_sync(0xffffffffu, a1, o);
            a2 += __shfl_xor_sync(0xffffffffu, a2, o);
            a3 += __shfl_xor_sync(0xffffffffu, a3, o);
            a4 += __shfl_xor_sync(0xffffffffu, a4, o);
        }
        if (t == 0) {
            float inv = 1.0f / a0;   // exact divide for final precision
            out[b * 4 + 0] = a1 * inv;
            out[b * 4 + 1] = a2 * inv;
            out[b * 4 + 2] = a3 * inv;
            out[b * 4 + 3] = a4 * inv;
        }
    }
}

// ---------------------------------------------------------------------------
extern "C" void kernel_launch(void* const* d_in, const int* in_sizes, int n_in,
                              void* d_out, int out_size)
{
    const float* boxes  = (const float*)d_in[0];
    const float* scores = (const float*)d_in[1];
    // Defensive: metadata order should be (boxes, scores); swap if sizes say otherwise.
    if (n_in >= 2 && in_sizes[0] == BATCH * NBOX && in_sizes[1] == BATCH * NBOX * 4) {
        const float* tmp = boxes; boxes = scores; scores = tmp;
    }
    float* out = (float*)d_out;

    dim3 grid(NBOX / THREADS, BATCH);
    adjusted_kernel<<<grid, THREADS>>>(boxes, scores);
    softmax_out_kernel<<<BATCH, 1024>>>(boxes, out);
}

// round 7
// speedup vs baseline: 1.6448x; 1.6448x over previous
#include <cuda_runtime.h>
#include <cuda_bf16.h>

#define BATCH   4
#define NBOX    8192
#define TILE    256
#define THREADS 256
#define ROWS    2
#define SPLIT   8
#define JCHUNK  (NBOX / SPLIT)   // 1024

// Scratch: per-split partial adjusted sums (no device allocs allowed).
__device__ float g_part[SPLIT][BATCH * NBOX];

// ---------------------------------------------------------------------------
// Kernel 1: partial adjusted[b][i] over a j-chunk.
// adjusted[b][i] = sum_j exp(-iou(i,j)/0.5) * scores[b][j]
// Grid: (NBOX/(THREADS*ROWS), BATCH, SPLIT) = (16, 4, 8) = 512 CTAs.
// ---------------------------------------------------------------------------
__global__ __launch_bounds__(THREADS)
void adjusted_kernel(const float* __restrict__ boxes,
                     const float* __restrict__ scores)
{
    const int b = blockIdx.y;
    const int z = blockIdx.z;
    const int i0 = blockIdx.x * (THREADS * ROWS) + threadIdx.x;
    const int i1 = i0 + THREADS;

    const float4* __restrict__ box4 = reinterpret_cast<const float4*>(boxes) + (size_t)b * NBOX;
    const float*  __restrict__ sc   = scores + (size_t)b * NBOX;

    const float4 bi0 = box4[i0];
    const float4 bi1 = box4[i1];
    const float  area0 = (bi0.z - bi0.x) * (bi0.w - bi0.y);
    const float  area1 = (bi1.z - bi1.x) * (bi1.w - bi1.y);

    __shared__ float4 sbox[TILE];
    __shared__ float2 sas[TILE];   // (area_j, score_j)

    // exp(-iou/0.5) = exp2( iou * (-2/ln2) )
    const float C = -2.8853900817779268f;

    // Kahan-compensated across tiles (order-stable, deterministic)
    float acc0 = 0.0f, comp0 = 0.0f;
    float acc1 = 0.0f, comp1 = 0.0f;

    const int jbase = z * JCHUNK;
    for (int jt = 0; jt < JCHUNK; jt += TILE) {
        __syncthreads();
        {
            float4 bj = box4[jbase + jt + threadIdx.x];
            sbox[threadIdx.x] = bj;
            sas[threadIdx.x]  = make_float2((bj.z - bj.x) * (bj.w - bj.y),
                                            sc[jbase + jt + threadIdx.x]);
        }
        __syncthreads();

        float p0 = 0.0f, p1 = 0.0f;
        #pragma unroll 8
        for (int j = 0; j < TILE; ++j) {
            const float4 bj = sbox[j];
            const float2 as = sas[j];

            // row 0
            {
                float iw = fmaxf(fminf(bi0.z, bj.z) - fmaxf(bi0.x, bj.x), 0.0f);
                float ih = fmaxf(fminf(bi0.w, bj.w) - fmaxf(bi0.y, bj.y), 0.0f);
                float inter = iw * ih;
                float uni   = (area0 + as.x) - inter;
                float r; asm("rcp.approx.ftz.f32 %0, %1;" : "=f"(r) : "f"(uni));
                float t = (inter * C) * r;
                float w; asm("ex2.approx.ftz.f32 %0, %1;" : "=f"(w) : "f"(t));
                p0 = fmaf(w, as.y, p0);
            }
            // row 1
            {
                float iw = fmaxf(fminf(bi1.z, bj.z) - fmaxf(bi1.x, bj.x), 0.0f);
                float ih = fmaxf(fminf(bi1.w, bj.w) - fmaxf(bi1.y, bj.y), 0.0f);
                float inter = iw * ih;
                float uni   = (area1 + as.x) - inter;
                float r; asm("rcp.approx.ftz.f32 %0, %1;" : "=f"(r) : "f"(uni));
                float t = (inter * C) * r;
                float w; asm("ex2.approx.ftz.f32 %0, %1;" : "=f"(w) : "f"(t));
                p1 = fmaf(w, as.y, p1);
            }
        }

        // Kahan add of tile partials (use __f*_rn so it can't be reassociated)
        {
            float y = __fsub_rn(p0, comp0);
            float s = __fadd_rn(acc0, y);
            comp0   = __fsub_rn(__fsub_rn(s, acc0), y);
            acc0    = s;
        }
        {
            float y = __fsub_rn(p1, comp1);
            float s = __fadd_rn(acc1, y);
            comp1   = __fsub_rn(__fsub_rn(s, acc1), y);
            acc1    = s;
        }
    }

    g_part[z][b * NBOX + i0] = acc0;
    g_part[z][b * NBOX + i1] = acc1;
}

// ---------------------------------------------------------------------------
// Kernel 2: reduce split partials, per-batch softmax, weighted box average.
// ---------------------------------------------------------------------------
__global__ __launch_bounds__(1024)
void softmax_out_kernel(const float* __restrict__ boxes,
                        float* __restrict__ out)
{
    const int b = blockIdx.x;
    const int t = threadIdx.x;
    const float4* __restrict__ box4 = reinterpret_cast<const float4*>(boxes) + (size_t)b * NBOX;

    __shared__ float sadj[NBOX];           // 32 KB
    __shared__ float sred[32];
    __shared__ float s5[5][32];

    // ---- reduce split partials into shared (fixed order -> deterministic) ----
    for (int i = t; i < NBOX; i += 1024) {
        float a = g_part[0][b * NBOX + i];
        #pragma unroll
        for (int z = 1; z < SPLIT; ++z)
            a = __fadd_rn(a, g_part[z][b * NBOX + i]);
        sadj[i] = a;
    }
    __syncthreads();

    // ---- block max ----
    float m = -3.4e38f;
    for (int i = t; i < NBOX; i += 1024) m = fmaxf(m, sadj[i]);
    #pragma unroll
    for (int o = 16; o; o >>= 1) m = fmaxf(m, __shfl_xor_sync(0xffffffffu, m, o));
    if ((t & 31) == 0) sred[t >> 5] = m;
    __syncthreads();
    if (t < 32) {
        float v = sred[t];
        #pragma unroll
        for (int o = 16; o; o >>= 1) v = fmaxf(v, __shfl_xor_sync(0xffffffffu, v, o));
        if (t == 0) sred[0] = v;
    }
    __syncthreads();
    m = sred[0];

    // ---- weighted sums ----
    float se = 0.f, sx1 = 0.f, sy1 = 0.f, sx2 = 0.f, sy2 = 0.f;
    for (int i = t; i < NBOX; i += 1024) {
        float e = __expf(sadj[i] - m);
        float4 bx = box4[i];
        se  += e;
        sx1 = fmaf(e, bx.x, sx1);
        sy1 = fmaf(e, bx.y, sy1);
        sx2 = fmaf(e, bx.z, sx2);
        sy2 = fmaf(e, bx.w, sy2);
    }
    #pragma unroll
    for (int o = 16; o; o >>= 1) {
        se  += __shfl_xor_sync(0xffffffffu, se,  o);
        sx1 += __shfl_xor_sync(0xffffffffu, sx1, o);
        sy1 += __shfl_xor_sync(0xffffffffu, sy1, o);
        sx2 += __shfl_xor_sync(0xffffffffu, sx2, o);
        sy2 += __shfl_xor_sync(0xffffffffu, sy2, o);
    }
    if ((t & 31) == 0) {
        int w = t >> 5;
        s5[0][w] = se; s5[1][w] = sx1; s5[2][w] = sy1; s5[3][w] = sx2; s5[4][w] = sy2;
    }
    __syncthreads();
    if (t < 32) {
        float a0 = s5[0][t], a1 = s5[1][t], a2 = s5[2][t], a3 = s5[3][t], a4 = s5[4][t];
        #pragma unroll
        for (int o = 16; o; o >>= 1) {
            a0 += __shfl_xor_sync(0xffffffffu, a0, o);
            a1 += __shfl_xor_sync(0xffffffffu, a1, o);
            a2 += __shfl_xor_sync(0xffffffffu, a2, o);
            a3 += __shfl_xor_sync(0xffffffffu, a3, o);
            a4 += __shfl_xor_sync(0xffffffffu, a4, o);
        }
        if (t == 0) {
            float inv = 1.0f / a0;   // exact divide for final precision
            out[b * 4 + 0] = a1 * inv;
            out[b * 4 + 1] = a2 * inv;
            out[b * 4 + 2] = a3 * inv;
            out[b * 4 + 3] = a4 * inv;
        }
    }
}

// ---------------------------------------------------------------------------
extern "C" void kernel_launch(void* const* d_in, const int* in_sizes, int n_in,
                              void* d_out, int out_size)
{
    const float* boxes  = (const float*)d_in[0];
    const float* scores = (const float*)d_in[1];
    // Defensive: metadata order should be (boxes, scores); swap if sizes say otherwise.
    if (n_in >= 2 && in_sizes[0] == BATCH * NBOX && in_sizes[1] == BATCH * NBOX * 4) {
        const float* tmp = boxes; boxes = scores; scores = tmp;
    }
    float* out = (float*)d_out;

    dim3 grid(NBOX / (THREADS * ROWS), BATCH, SPLIT);
    adjusted_kernel<<<grid, THREADS>>>(boxes, scores);
    softmax_out_kernel<<<BATCH, 1024>>>(boxes, out);
}